// round 1
// baseline (speedup 1.0000x reference)
#include <cuda_runtime.h>

// ---------------------------------------------------------------------------
// DNN_SKalmanNet_GSS — batch-1 GEMV chain, HBM-bound (~499 MB weights/pass).
// 6 launches: build_inputs -> l1/l3 -> gru gi/gh (4 segs) -> gate -> l2a/l4a
//             -> l2b/l4b (writes d_out).
// Warp-per-row GEMV, float4 loads, x staged in dynamic shared memory.
// ---------------------------------------------------------------------------

#define XDIM 32
#define YDIM 32
#define H1   5120      // (X+Y)*10*8
#define H2   4096      // X*Y*4
#define HID  2048      // X*X + Y*Y
#define IN1  1120      // 2X + Y + X*Y
#define OUT1 1024
#define OUT2 1024

// Scratch (device globals: allocation-free)
__device__ float g_input1[IN1];
__device__ float g_input2[IN1];
__device__ float g_l1[H1];
__device__ float g_l3[H1];
__device__ float g_gi1[3 * HID];
__device__ float g_gh1[3 * HID];
__device__ float g_gi2[3 * HID];
__device__ float g_gh2[3 * HID];
__device__ float g_h1[HID];
__device__ float g_h2[HID];
__device__ float g_hid1[H2];
__device__ float g_hid2[H2];

struct Seg {
    const float* W;
    const float* x;
    const float* b;
    float*       y;
    int          rows;
    int          cols;
    int          act;   // 0 = none, 1 = relu
};
struct Segs { Seg s[4]; };

// input1 = [state_inno(32), diff_state(32), lin_err(32), Jacobian(1024)]
// input2 = [obs_inno(32),   diff_obs(32),   lin_err(32), Jacobian(1024)]
__global__ void build_inputs_k(const float* __restrict__ si,
                               const float* __restrict__ oi,
                               const float* __restrict__ ds,
                               const float* __restrict__ dob,
                               const float* __restrict__ le,
                               const float* __restrict__ J) {
    int i = blockIdx.x * blockDim.x + threadIdx.x;
    if (i >= IN1) return;
    float v1, v2;
    if (i < 32)       { v1 = si[i];      v2 = oi[i]; }
    else if (i < 64)  { v1 = ds[i - 32]; v2 = dob[i - 32]; }
    else if (i < 96)  { v1 = le[i - 64]; v2 = v1; }
    else              { v1 = J[i - 96];  v2 = v1; }
    g_input1[i] = v1;
    g_input2[i] = v2;
}

// Multi-segment warp-per-row GEMV. blockIdx.y selects segment.
// Dynamic smem must hold max(cols)*4 bytes for this launch.
__global__ void gemv_multi_k(Segs segs) {
    Seg s = segs.s[blockIdx.y];
    extern __shared__ float4 sx[];
    const int c4 = s.cols >> 2;

    // Stage x into shared memory (conflict-free float4 stride)
    const float4* __restrict__ xv = (const float4*)s.x;
    for (int j = threadIdx.x; j < c4; j += blockDim.x) sx[j] = xv[j];
    __syncthreads();

    const int lane = threadIdx.x & 31;
    const int warp = (blockIdx.x * blockDim.x + threadIdx.x) >> 5;
    const int nw   = (gridDim.x * blockDim.x) >> 5;

    for (int row = warp; row < s.rows; row += nw) {
        const float4* __restrict__ Wr = (const float4*)s.W + (size_t)row * c4;
        float acc = 0.f;
        #pragma unroll 4
        for (int j = lane; j < c4; j += 32) {
            float4 w  = Wr[j];
            float4 xx = sx[j];
            acc = fmaf(w.x, xx.x, acc);
            acc = fmaf(w.y, xx.y, acc);
            acc = fmaf(w.z, xx.z, acc);
            acc = fmaf(w.w, xx.w, acc);
        }
        #pragma unroll
        for (int o = 16; o; o >>= 1) acc += __shfl_xor_sync(0xffffffffu, acc, o);
        if (lane == 0) {
            float v = acc + s.b[row];
            if (s.act) v = fmaxf(v, 0.f);
            s.y[row] = v;
        }
    }
}

__device__ __forceinline__ float sigmoidf_(float x) {
    return 1.f / (1.f + __expf(-x));
}

// PyTorch GRU gate combine (order r,z,n): h' = (1-z)*n + z*h
__global__ void gru_gate_k(const float* __restrict__ hn1,
                           const float* __restrict__ hn2) {
    int i = blockIdx.x * blockDim.x + threadIdx.x;
    if (i >= HID) return;
    const float* gi; const float* gh; const float* hp; float* h;
    if (blockIdx.y == 0) { gi = g_gi1; gh = g_gh1; hp = hn1; h = g_h1; }
    else                 { gi = g_gi2; gh = g_gh2; hp = hn2; h = g_h2; }
    float r = sigmoidf_(gi[i]           + gh[i]);
    float z = sigmoidf_(gi[i + HID]     + gh[i + HID]);
    float n = tanhf(gi[i + 2 * HID] + r * gh[i + 2 * HID]);
    h[i] = (1.f - z) * n + z * hp[i];
}

static inline Seg mkseg(const float* W, const float* x, const float* b, float* y,
                        int rows, int cols, int act) {
    Seg s; s.W = W; s.x = x; s.b = b; s.y = y; s.rows = rows; s.cols = cols; s.act = act;
    return s;
}

extern "C" void kernel_launch(void* const* d_in, const int* in_sizes, int n_in,
                              void* d_out, int out_size) {
    // Inputs in reference-signature order
    const float* state_inno = (const float*)d_in[0];
    const float* obs_inno   = (const float*)d_in[1];
    const float* diff_state = (const float*)d_in[2];
    const float* diff_obs   = (const float*)d_in[3];
    const float* lin_err    = (const float*)d_in[4];
    const float* Jacobian   = (const float*)d_in[5];
    const float* l1_W  = (const float*)d_in[6];
    const float* l1_b  = (const float*)d_in[7];
    const float* g1Wih = (const float*)d_in[8];
    const float* g1Whh = (const float*)d_in[9];
    const float* g1bih = (const float*)d_in[10];
    const float* g1bhh = (const float*)d_in[11];
    const float* l2_W1 = (const float*)d_in[12];
    const float* l2_b1 = (const float*)d_in[13];
    const float* l2_W2 = (const float*)d_in[14];
    const float* l2_b2 = (const float*)d_in[15];
    const float* l3_W  = (const float*)d_in[16];
    const float* l3_b  = (const float*)d_in[17];
    const float* g2Wih = (const float*)d_in[18];
    const float* g2Whh = (const float*)d_in[19];
    const float* g2bih = (const float*)d_in[20];
    const float* g2bhh = (const float*)d_in[21];
    const float* l4_W1 = (const float*)d_in[22];
    const float* l4_b1 = (const float*)d_in[23];
    const float* l4_W2 = (const float*)d_in[24];
    const float* l4_b2 = (const float*)d_in[25];
    const float* hn1   = (const float*)d_in[26];
    const float* hn2   = (const float*)d_in[27];

    float* out = (float*)d_out;   // [Pk(1024), Sk(1024)]

    // Device addresses of scratch symbols (capture-safe: not a stream op)
    float *p_in1, *p_in2, *p_l1, *p_l3;
    float *p_gi1, *p_gh1, *p_gi2, *p_gh2, *p_h1, *p_h2, *p_hid1, *p_hid2;
    cudaGetSymbolAddress((void**)&p_in1,  g_input1);
    cudaGetSymbolAddress((void**)&p_in2,  g_input2);
    cudaGetSymbolAddress((void**)&p_l1,   g_l1);
    cudaGetSymbolAddress((void**)&p_l3,   g_l3);
    cudaGetSymbolAddress((void**)&p_gi1,  g_gi1);
    cudaGetSymbolAddress((void**)&p_gh1,  g_gh1);
    cudaGetSymbolAddress((void**)&p_gi2,  g_gi2);
    cudaGetSymbolAddress((void**)&p_gh2,  g_gh2);
    cudaGetSymbolAddress((void**)&p_h1,   g_h1);
    cudaGetSymbolAddress((void**)&p_h2,   g_h2);
    cudaGetSymbolAddress((void**)&p_hid1, g_hid1);
    cudaGetSymbolAddress((void**)&p_hid2, g_hid2);

    const Seg z = mkseg(nullptr, nullptr, nullptr, nullptr, 0, 0, 0);

    // 1) concat inputs
    build_inputs_k<<<(IN1 + 255) / 256, 256>>>(state_inno, obs_inno, diff_state,
                                               diff_obs, lin_err, Jacobian);

    // 2) l1_out = relu(l1_W @ in1 + b) ; l3_out = relu(l3_W @ in2 + b)
    {
        Segs sg;
        sg.s[0] = mkseg(l1_W, p_in1, l1_b, p_l1, H1, IN1, 1);
        sg.s[1] = mkseg(l3_W, p_in2, l3_b, p_l3, H1, IN1, 1);
        sg.s[2] = z; sg.s[3] = z;
        gemv_multi_k<<<dim3(H1 / 8, 2), 256, IN1 * sizeof(float)>>>(sg);
    }

    // 3) GRU pre-gates: gi = Wih@l_out + bih ; gh = Whh@hn + bhh (both branches)
    {
        Segs sg;
        sg.s[0] = mkseg(g1Wih, p_l1, g1bih, p_gi1, 3 * HID, H1,  0);
        sg.s[1] = mkseg(g1Whh, hn1,  g1bhh, p_gh1, 3 * HID, HID, 0);
        sg.s[2] = mkseg(g2Wih, p_l3, g2bih, p_gi2, 3 * HID, H1,  0);
        sg.s[3] = mkseg(g2Whh, hn2,  g2bhh, p_gh2, 3 * HID, HID, 0);
        gemv_multi_k<<<dim3((3 * HID) / 8, 4), 256, H1 * sizeof(float)>>>(sg);
    }

    // 4) gate combine -> h1, h2
    gru_gate_k<<<dim3(HID / 256, 2), 256>>>(hn1, hn2);

    // 5) hidden = relu(W1 @ h + b1) (both branches)
    {
        Segs sg;
        sg.s[0] = mkseg(l2_W1, p_h1, l2_b1, p_hid1, H2, HID, 1);
        sg.s[1] = mkseg(l4_W1, p_h2, l4_b1, p_hid2, H2, HID, 1);
        sg.s[2] = z; sg.s[3] = z;
        gemv_multi_k<<<dim3(H2 / 8, 2), 256, HID * sizeof(float)>>>(sg);
    }

    // 6) Pk = W2 @ hidden + b2 ; Sk likewise -> d_out
    {
        Segs sg;
        sg.s[0] = mkseg(l2_W2, p_hid1, l2_b2, out,        OUT1, H2, 0);
        sg.s[1] = mkseg(l4_W2, p_hid2, l4_b2, out + OUT1, OUT2, H2, 0);
        sg.s[2] = z; sg.s[3] = z;
        gemv_multi_k<<<dim3(OUT1 / 8, 2), 256, H2 * sizeof(float)>>>(sg);
    }
    (void)in_sizes; (void)n_in; (void)out_size;
}